// round 13
// baseline (speedup 1.0000x reference)
#include <cuda_runtime.h>
#include <cuda_fp16.h>
#include <cstdint>

// ---------------------------------------------------------------------------
// PCT position-embedding + 4 offset-attention SA layers. B=8, C=256, D=64,
// N=2048. fp16 mma.sync m16n8k16 (fp32 accum), PSCALE'd softmax probs.
// Softmax-free: energy GEMM emits p~ = PSCALE*exp(e - groupmax) fp16 with
// per-(row, 32-col-group) stats reduced purely in-quad (no smem rounds);
// rowstats -> s[n,t] (t = 64 column groups); xr GEMM applies s per fragment.
// ---------------------------------------------------------------------------

#define B_   8
#define C_   256
#define D_   64
#define N_   2048
#define PSCALE 32768.0f
#define NT_  64                        // N_/32 column groups

__device__ __half g_pos[B_ * C_ * N_];
__device__ float  g_h0 [B_ * C_ * N_];
__device__ __half g_hp [B_ * C_ * N_];
__device__ __half g_xh [B_ * C_ * N_];
__device__ __half g_q  [B_ * D_ * N_];
__device__ __half g_qT [B_ * N_ * D_];
__device__ __half g_val[B_ * C_ * N_];
__device__ __half g_dh [B_ * C_ * N_];
__device__ __half g_ath[(long long)B_ * N_ * N_];   // p~ (fp16)
__device__ float2 g_tstat[(long)B_ * NT_ * N_];     // {groupmax, groupsum}
__device__ float  g_s   [(long)B_ * NT_ * N_];      // s[n,t]
__device__ __half g_wh [655360];

__device__ __forceinline__ uint32_t smem_u32(const void* p) {
    return (uint32_t)__cvta_generic_to_shared(p);
}
__device__ __forceinline__ uint32_t h2u(__half2 h) {
    return *reinterpret_cast<uint32_t*>(&h);
}

// ---------------------------------------------------------------------------
// warp-tile compute: 64x32 warp tile, fp16 m16n8k16, fp32 accum.
// SCALE variant multiplies B fragments by per-k fp32 scales from sst[32]
// (this warp's 32-col group) and accumulates scaled column sums.
// ---------------------------------------------------------------------------
template <bool SCALE>
__device__ __forceinline__ void compute_tile(
    const __half* __restrict__ Asb, const __half* __restrict__ Bsb,
    float acc[4][4][4], int lane, int wm0, int wn0,
    const float* __restrict__ sst, float* __restrict__ csumF)
{
    const int tg = lane & 3;
#pragma unroll
    for (int ks = 0; ks < 2; ks++) {
        uint32_t a[4][4];
#pragma unroll
        for (int mt = 0; mt < 4; mt++) {
            const __half* pa = Asb + (wm0 + mt * 16 + (lane & 15)) * 40
                             + ks * 16 + (lane >> 4) * 8;
            uint32_t ad = smem_u32(pa);
            asm volatile("ldmatrix.sync.aligned.m8n8.x4.shared.b16 {%0,%1,%2,%3}, [%4];"
                : "=r"(a[mt][0]), "=r"(a[mt][1]), "=r"(a[mt][2]), "=r"(a[mt][3])
                : "r"(ad));
        }
        uint32_t b[4][2];
#pragma unroll
        for (int j = 0; j < 2; j++) {
            const __half* pb = Bsb
                + (ks * 16 + (lane & 7) + ((lane >> 3) & 1) * 8) * 136
                + wn0 + j * 16 + (lane >> 4) * 8;
            uint32_t bd = smem_u32(pb);
            uint32_t r0, r1, r2, r3;
            asm volatile("ldmatrix.sync.aligned.m8n8.x4.trans.shared.b16 {%0,%1,%2,%3}, [%4];"
                : "=r"(r0), "=r"(r1), "=r"(r2), "=r"(r3) : "r"(bd));
            b[2 * j][0] = r0; b[2 * j][1] = r1;
            b[2 * j + 1][0] = r2; b[2 * j + 1][1] = r3;
        }
        if (SCALE) {
            float2 sA = *reinterpret_cast<const float2*>(&sst[ks * 16 + 2 * tg]);
            float2 sB = *reinterpret_cast<const float2*>(&sst[ks * 16 + 8 + 2 * tg]);
#pragma unroll
            for (int nt = 0; nt < 4; nt++) {
                __half2 h0v = *reinterpret_cast<__half2*>(&b[nt][0]);
                float2 f0 = __half22float2(h0v);
                f0.x *= sA.x; f0.y *= sA.y;
                b[nt][0] = h2u(__floats2half2_rn(f0.x, f0.y));
                __half2 h1v = *reinterpret_cast<__half2*>(&b[nt][1]);
                float2 f1 = __half22float2(h1v);
                f1.x *= sB.x; f1.y *= sB.y;
                b[nt][1] = h2u(__floats2half2_rn(f1.x, f1.y));
                csumF[nt] += (f0.x + f0.y) + (f1.x + f1.y);
            }
        }
#pragma unroll
        for (int mt = 0; mt < 4; mt++)
#pragma unroll
            for (int nt = 0; nt < 4; nt++) {
                asm volatile(
                    "mma.sync.aligned.m16n8k16.row.col.f32.f16.f16.f32 "
                    "{%0,%1,%2,%3}, {%4,%5,%6,%7}, {%8,%9}, {%0,%1,%2,%3};"
                    : "+f"(acc[mt][nt][0]), "+f"(acc[mt][nt][1]),
                      "+f"(acc[mt][nt][2]), "+f"(acc[mt][nt][3])
                    : "r"(a[mt][0]), "r"(a[mt][1]), "r"(a[mt][2]), "r"(a[mt][3]),
                      "r"(b[nt][0]), "r"(b[nt][1]));
            }
    }
}

// ---------------------------------------------------------------------------
// prep kernel: weights + x to fp16, pos (fp16).
// ---------------------------------------------------------------------------
#define SEG_W1   65536L
#define SEG_QV   327680L
#define SEG_WT   262144L
#define SEG_X    ((long)B_ * C_ * N_)
#define PREP_TOT (SEG_W1 + SEG_QV + SEG_WT + SEG_X + SEG_X)

__global__ void prep_kernel(const float* __restrict__ conv1_w,
                            const float* __restrict__ Wqk,
                            const float* __restrict__ Wv,
                            const float* __restrict__ Wt,
                            const float* __restrict__ x,
                            const float* __restrict__ convpos,
                            const float* __restrict__ xyz)
{
    long i = (long)blockIdx.x * 256 + threadIdx.x;
    if (i >= PREP_TOT) return;
    if (i < SEG_W1) {
        g_wh[i] = __float2half_rn(conv1_w[i]);
    } else if (i < SEG_W1 + SEG_QV) {
        long j = i - SEG_W1;
        int layer = (int)(j / 81920);
        long o = j % 81920;
        float v = (o < 16384) ? Wqk[(long)layer * 16384 + o]
                              : Wv[(long)layer * 65536 + (o - 16384)];
        g_wh[i] = __float2half_rn(v);
    } else if (i < SEG_W1 + SEG_QV + SEG_WT) {
        g_wh[i] = __float2half_rn(Wt[i - SEG_W1 - SEG_QV]);
    } else if (i < SEG_W1 + SEG_QV + SEG_WT + SEG_X) {
        long j = i - SEG_W1 - SEG_QV - SEG_WT;
        g_xh[j] = __float2half_rn(x[j]);
    } else {
        long j = i - SEG_W1 - SEG_QV - SEG_WT - SEG_X;
        int n = (int)(j % N_);
        int c = (int)((j / N_) % C_);
        int b = (int)(j / ((long)C_ * N_));
        const float* pp = xyz + ((long)b * N_ + n) * 3;
        g_pos[j] = __float2half_rn(
            convpos[c * 3 + 0] * pp[0] + convpos[c * 3 + 1] * pp[1]
            + convpos[c * 3 + 2] * pp[2]);
    }
}

// ---------------------------------------------------------------------------
// fp16 GEMM, block tile 128x128, 4-stage cp.async ring, 1 barrier/stage.
// ---------------------------------------------------------------------------
enum { EPI_BN_RELU = 0, EPI_QVAL = 1, EPI_EXPTILE = 2, EPI_COLSCALE = 3,
       EPI_T_UPDATE = 4 };

#define TG_STAGES   4
#define TG_AS_STR   (128 * 40)
#define TG_BS_STR   (32 * 136)
#define TG_RING_B   (TG_STAGES * (TG_AS_STR + TG_BS_STR) * 2)
#define TG_CSB_B    (TG_RING_B)
#define TG_SR_B     (TG_CSB_B + 128 * 4)
#define TG_SMEM     (TG_SR_B + TG_STAGES * 128 * 4)   // s ring: 4 x (4 grp x 32)

#define SCN_ ((long)C_ * N_)

template <int EPI>
__global__ void __launch_bounds__(256, 2)
tgemm(const __half* __restrict__ A, long aStride, int M, int K,
      const __half* __restrict__ Bm, long bStride,
      float* __restrict__ Cf, __half* __restrict__ Ch, long cStride,
      const float* __restrict__ bias,
      const float* __restrict__ bng, const float* __restrict__ bnb,
      const float* __restrict__ bnm, const float* __restrict__ bnv,
      const float* __restrict__ hres, long hresStride,
      const __half* __restrict__ posB,
      __half* __restrict__ hpOut,
      float* __restrict__ out2, long out2Stride,
      __half* __restrict__ qB, __half* __restrict__ qTB,
      float2* __restrict__ tstatOut, const float* __restrict__ sArr)
{
    extern __shared__ char smd[];
    __half* AsBase = reinterpret_cast<__half*>(smd);
    __half* BsBase = AsBase + TG_STAGES * TG_AS_STR;
    float* csb   = reinterpret_cast<float*>(smd + TG_CSB_B);
    float* sring = reinterpret_cast<float*>(smd + TG_SR_B);

    const int bz = blockIdx.z;
    const __half* Ab = A + (long)bz * aStride;
    const __half* Bb = Bm + (long)bz * bStride;
    // s rows for this block's 4 column groups
    const float* sBase = (EPI == EPI_COLSCALE)
        ? (sArr + (((long)bz * NT_ + blockIdx.x * 4) << 11)) : nullptr;

    const int m0 = blockIdx.y * 128;
    const int n0 = blockIdx.x * 128;
    const int t  = threadIdx.x;
    const int lane = t & 31;
    const int w    = t >> 5;
    const int g  = lane >> 2, tg = lane & 3;
    const int wm0 = (w >> 2) * 64, wn0 = (w & 3) * 32;

    float acc[4][4][4];
#pragma unroll
    for (int i = 0; i < 4; i++)
#pragma unroll
        for (int j = 0; j < 4; j++)
#pragma unroll
            for (int k = 0; k < 4; k++) acc[i][j][k] = 0.f;

    float csumF[4] = {0.f, 0.f, 0.f, 0.f};

    const int aRow = t >> 2, aCg = (t & 3) * 8;
    const int bRow = t >> 4, bCg = (t & 15) * 8;
    const int nStages = K >> 5;

    // prologue
#pragma unroll
    for (int s = 0; s < TG_STAGES - 1; s++) {
        if (s < nStages) {
            const int k0 = s * 32;
            __half* As = AsBase + s * TG_AS_STR;
            __half* Bs = BsBase + s * TG_BS_STR;
#pragma unroll
            for (int h = 0; h < 2; h++) {
                int row = aRow + h * 64;
                if (m0 + row < M) {
                    uint32_t dst = smem_u32(As + row * 40 + aCg);
                    const __half* src = Ab + (long)(m0 + row) * K + k0 + aCg;
                    asm volatile("cp.async.cg.shared.global [%0], [%1], 16;" :: "r"(dst), "l"(src));
                }
            }
#pragma unroll
            for (int h = 0; h < 2; h++) {
                int row = bRow + h * 16;
                uint32_t dst = smem_u32(Bs + row * 136 + bCg);
                const __half* src = Bb + (long)(k0 + row) * N_ + n0 + bCg;
                asm volatile("cp.async.cg.shared.global [%0], [%1], 16;" :: "r"(dst), "l"(src));
            }
            if (EPI == EPI_COLSCALE && t < 32) {
                int grp = t >> 3, q4 = (t & 7) * 4;
                uint32_t dst = smem_u32(sring + s * 128 + grp * 32 + q4);
                const float* src = sBase + ((long)grp << 11) + k0 + q4;
                asm volatile("cp.async.cg.shared.global [%0], [%1], 16;" :: "r"(dst), "l"(src));
            }
        }
        asm volatile("cp.async.commit_group;");
    }

    for (int s = 0; s < nStages; s++) {
        const int buf = s & (TG_STAGES - 1);
        asm volatile("cp.async.wait_group %0;" :: "n"(TG_STAGES - 2));
        __syncthreads();

        const int sn = s + TG_STAGES - 1;
        if (sn < nStages) {
            const int k0 = sn * 32, nb = sn & (TG_STAGES - 1);
            __half* As = AsBase + nb * TG_AS_STR;
            __half* Bs = BsBase + nb * TG_BS_STR;
#pragma unroll
            for (int h = 0; h < 2; h++) {
                int row = aRow + h * 64;
                if (m0 + row < M) {
                    uint32_t dst = smem_u32(As + row * 40 + aCg);
                    const __half* src = Ab + (long)(m0 + row) * K + k0 + aCg;
                    asm volatile("cp.async.cg.shared.global [%0], [%1], 16;" :: "r"(dst), "l"(src));
                }
            }
#pragma unroll
            for (int h = 0; h < 2; h++) {
                int row = bRow + h * 16;
                uint32_t dst = smem_u32(Bs + row * 136 + bCg);
                const __half* src = Bb + (long)(k0 + row) * N_ + n0 + bCg;
                asm volatile("cp.async.cg.shared.global [%0], [%1], 16;" :: "r"(dst), "l"(src));
            }
            if (EPI == EPI_COLSCALE && t < 32) {
                int grp = t >> 3, q4 = (t & 7) * 4;
                uint32_t dst = smem_u32(sring + nb * 128 + grp * 32 + q4);
                const float* src = sBase + ((long)grp << 11) + k0 + q4;
                asm volatile("cp.async.cg.shared.global [%0], [%1], 16;" :: "r"(dst), "l"(src));
            }
        }
        asm volatile("cp.async.commit_group;");

        const __half* AsC = AsBase + buf * TG_AS_STR;
        const __half* BsC = BsBase + buf * TG_BS_STR;
        compute_tile<EPI == EPI_COLSCALE>(AsC, BsC, acc, lane, wm0, wn0,
                                          sring + buf * 128 + (w & 3) * 32, csumF);
    }

    const long cOff = (long)bz * cStride;

    // ------- EXPTILE epilogue: per-(row, 32-col-group) stats, quad-only -------
    if (EPI == EPI_EXPTILE) {
        const int tileG = blockIdx.x * 4 + (w & 3);    // global column group
#pragma unroll
        for (int mt = 0; mt < 4; mt++)
#pragma unroll
            for (int hf = 0; hf < 2; hf++) {
                // group max over this warp's 32 cols (quad shuffles)
                float mval = -3.4e38f;
#pragma unroll
                for (int nt = 0; nt < 4; nt++) {
                    mval = fmaxf(mval, acc[mt][nt][hf * 2 + 0]);
                    mval = fmaxf(mval, acc[mt][nt][hf * 2 + 1]);
                }
                mval = fmaxf(mval, __shfl_xor_sync(0xffffffffu, mval, 1));
                mval = fmaxf(mval, __shfl_xor_sync(0xffffffffu, mval, 2));
                // exp + group sum
                float s2 = 0.f;
                float e[4][2];
#pragma unroll
                for (int nt = 0; nt < 4; nt++) {
                    e[nt][0] = __expf(acc[mt][nt][hf * 2 + 0] - mval);
                    e[nt][1] = __expf(acc[mt][nt][hf * 2 + 1] - mval);
                    s2 += e[nt][0] + e[nt][1];
                }
                s2 += __shfl_xor_sync(0xffffffffu, s2, 1);
                s2 += __shfl_xor_sync(0xffffffffu, s2, 2);
                // write p~ and stats
                const int r = m0 + wm0 + mt * 16 + g + hf * 8;
#pragma unroll
                for (int nt = 0; nt < 4; nt++) {
                    const int cb = n0 + wn0 + nt * 8 + 2 * tg;
                    *reinterpret_cast<__half2*>(Ch + cOff + (long)r * N_ + cb) =
                        __floats2half2_rn(PSCALE * e[nt][0], PSCALE * e[nt][1]);
                }
                if (tg == 0)
                    tstatOut[(((long)bz * NT_ + tileG) << 11) + r] =
                        make_float2(mval, s2);
            }
        return;
    }

    if (EPI == EPI_COLSCALE) {
        __syncthreads();
#pragma unroll
        for (int nt = 0; nt < 4; nt++) {
            csumF[nt] += __shfl_xor_sync(0xffffffffu, csumF[nt], 1);
            csumF[nt] += __shfl_xor_sync(0xffffffffu, csumF[nt], 2);
        }
        if (w < 4 && tg == 0) {
#pragma unroll
            for (int nt = 0; nt < 4; nt++)
                csb[wn0 + nt * 8 + g] = 1.f / (PSCALE * 1e-9f + csumF[nt]);
        }
        __syncthreads();
    }

#pragma unroll
    for (int mt = 0; mt < 4; mt++) {
#pragma unroll
        for (int half_ = 0; half_ < 2; half_++) {
            const int r = m0 + wm0 + mt * 16 + g + half_ * 8;
            if (r >= M) continue;

            float sc = 1.f, sh = 0.f, bsv = 0.f;
            if (EPI == EPI_BN_RELU || EPI == EPI_T_UPDATE) {
                float inv = rsqrtf(bnv[r] + 1e-5f);
                sc = bng[r] * inv; sh = bnb[r] - bnm[r] * sc;
            }
            if (EPI == EPI_T_UPDATE) bsv = bias[r];

#pragma unroll
            for (int nt = 0; nt < 4; nt++) {
                const int cb = n0 + wn0 + nt * 8 + 2 * tg;
                float v0 = acc[mt][nt][half_ * 2 + 0];
                float v1 = acc[mt][nt][half_ * 2 + 1];
                long rowoff = (long)r * N_ + cb;

                if (EPI == EPI_BN_RELU) {
                    v0 = fmaxf(fmaf(v0, sc, sh), 0.f);
                    v1 = fmaxf(fmaf(v1, sc, sh), 0.f);
                    *reinterpret_cast<float2*>(Cf + cOff + rowoff) = make_float2(v0, v1);
                    const __half* pb = posB + (long)bz * SCN_;
                    float2 p2 = __half22float2(
                        *reinterpret_cast<const __half2*>(pb + rowoff));
                    __half2* hbp = reinterpret_cast<__half2*>(
                        hpOut + (long)bz * SCN_ + rowoff);
                    *hbp = __floats2half2_rn(v0 + p2.x, v1 + p2.y);
                } else if (EPI == EPI_QVAL) {
                    if (r < 64) {
                        __half q0 = __float2half_rn(v0), q1 = __float2half_rn(v1);
                        __half* qb = qB + (long)bz * ((long)D_ * N_);
                        *reinterpret_cast<__half2*>(qb + (long)r * N_ + cb) =
                            __halves2half2(q0, q1);
                        __half* qt = qTB + (long)bz * ((long)N_ * D_);
                        qt[(long)cb * D_ + r]       = q0;
                        qt[(long)(cb + 1) * D_ + r] = q1;
                    } else {
                        float bv2 = bias[r - 64];
                        long vo = (long)(r - 64) * N_ + cb;
                        *reinterpret_cast<__half2*>(Ch + cOff + vo) =
                            __floats2half2_rn(v0 + bv2, v1 + bv2);
                    }
                } else if (EPI == EPI_COLSCALE) {
                    float i0 = csb[cb - n0], i1 = csb[cb - n0 + 1];
                    const float* hb = hres + (long)bz * hresStride;
                    float2 h2 = *reinterpret_cast<const float2*>(hb + rowoff);
                    *reinterpret_cast<__half2*>(Ch + cOff + rowoff) =
                        __floats2half2_rn(h2.x - v0 * i0, h2.y - v1 * i1);
                } else { // EPI_T_UPDATE
                    v0 = fmaxf(fmaf(v0 + bsv, sc, sh), 0.f);
                    v1 = fmaxf(fmaf(v1 + bsv, sc, sh), 0.f);
                    const float* hb = hres + (long)bz * hresStride;
                    float2 h2 = *reinterpret_cast<const float2*>(hb + rowoff);
                    float o0 = v0 + h2.x, o1 = v1 + h2.y;
                    float* ob = out2 + (long)bz * out2Stride;
                    *reinterpret_cast<float2*>(ob + rowoff) = make_float2(o0, o1);
                    if (hpOut) {
                        const __half* pb = posB + (long)bz * SCN_;
                        float2 p2 = __half22float2(
                            *reinterpret_cast<const __half2*>(pb + rowoff));
                        __half2* hb2 = reinterpret_cast<__half2*>(
                            hpOut + (long)bz * SCN_ + rowoff);
                        *hb2 = __floats2half2_rn(o0 + p2.x, o1 + p2.y);
                    }
                }
            }
        }
    }
}

// ---------------------------------------------------------------------------
// rowstats: per (b, n) row, combine 64 group stats -> s[n, t].
// ---------------------------------------------------------------------------
__global__ void __launch_bounds__(256)
rowstats_kernel(const float2* __restrict__ tstat, float* __restrict__ sarr)
{
    int idx = blockIdx.x * 256 + threadIdx.x;
    int b = idx >> 11, n = idx & 2047;
    float tm[NT_], ts[NT_];
    float rmax = -3.4e38f;
#pragma unroll
    for (int t = 0; t < NT_; t++) {
        float2 v = tstat[(((long)b * NT_ + t) << 11) + n];
        tm[t] = v.x; ts[t] = v.y;
        rmax = fmaxf(rmax, v.x);
    }
    float rsum = 0.f;
#pragma unroll
    for (int t = 0; t < NT_; t++) {
        tm[t] = __expf(tm[t] - rmax);
        rsum += ts[t] * tm[t];
    }
    float rinv = 1.f / rsum;
#pragma unroll
    for (int t = 0; t < NT_; t++)
        sarr[(((long)b * NT_ + t) << 11) + n] = tm[t] * rinv;
}

// ---------------------------------------------------------------------------
extern "C" void kernel_launch(void* const* d_in, const int* in_sizes, int n_in,
                              void* d_out, int out_size)
{
    (void)in_sizes; (void)n_in; (void)out_size;

    const float* x       = (const float*)d_in[0];
    const float* xyz     = (const float*)d_in[1];
    const float* conv1_w = (const float*)d_in[2];
    const float* convpos = (const float*)d_in[3];
    const float* bn1_g   = (const float*)d_in[4];
    const float* bn1_b   = (const float*)d_in[5];
    const float* bn1_m   = (const float*)d_in[6];
    const float* bn1_v   = (const float*)d_in[7];
    const float* Wqk     = (const float*)d_in[8];
    const float* Wv      = (const float*)d_in[9];
    const float* bv      = (const float*)d_in[10];
    const float* Wt      = (const float*)d_in[11];
    const float* bt      = (const float*)d_in[12];
    const float* bng     = (const float*)d_in[13];
    const float* bnb     = (const float*)d_in[14];
    const float* bnm     = (const float*)d_in[15];
    const float* bnv     = (const float*)d_in[16];
    float* out = (float*)d_out;

    float  *h0, *sarr;
    float2 *tstat;
    __half *pos, *hp, *xh, *q, *qT, *val, *dh, *ath, *wh;
    cudaGetSymbolAddress((void**)&pos,   g_pos);
    cudaGetSymbolAddress((void**)&h0,    g_h0);
    cudaGetSymbolAddress((void**)&hp,    g_hp);
    cudaGetSymbolAddress((void**)&xh,    g_xh);
    cudaGetSymbolAddress((void**)&q,     g_q);
    cudaGetSymbolAddress((void**)&qT,    g_qT);
    cudaGetSymbolAddress((void**)&val,   g_val);
    cudaGetSymbolAddress((void**)&dh,    g_dh);
    cudaGetSymbolAddress((void**)&ath,   g_ath);
    cudaGetSymbolAddress((void**)&wh,    g_wh);
    cudaGetSymbolAddress((void**)&tstat, g_tstat);
    cudaGetSymbolAddress((void**)&sarr,  g_s);

    cudaFuncSetAttribute(tgemm<EPI_BN_RELU>,  cudaFuncAttributeMaxDynamicSharedMemorySize, TG_SMEM);
    cudaFuncSetAttribute(tgemm<EPI_QVAL>,     cudaFuncAttributeMaxDynamicSharedMemorySize, TG_SMEM);
    cudaFuncSetAttribute(tgemm<EPI_EXPTILE>,  cudaFuncAttributeMaxDynamicSharedMemorySize, TG_SMEM);
    cudaFuncSetAttribute(tgemm<EPI_COLSCALE>, cudaFuncAttributeMaxDynamicSharedMemorySize, TG_SMEM);
    cudaFuncSetAttribute(tgemm<EPI_T_UPDATE>, cudaFuncAttributeMaxDynamicSharedMemorySize, TG_SMEM);

    const long SCN = (long)C_ * N_;
    const long SDN = (long)D_ * N_;
    const long SNN = (long)N_ * N_;
    const long SND = (long)N_ * D_;
    const long SOUT = (long)4 * C_ * N_;

    __half* w_conv1 = wh;
    __half* w_qv    = wh + SEG_W1;
    __half* w_t     = wh + SEG_W1 + SEG_QV;

    dim3 blk(256);
    dim3 gC (N_ / 128, 2, B_);
    dim3 gQV(N_ / 128, 3, B_);
    dim3 gE (N_ / 128, N_ / 128, B_);

    prep_kernel<<<(int)((PREP_TOT + 255) / 256), blk>>>(conv1_w, Wqk, Wv, Wt, x,
                                                        convpos, xyz);

    // h0 = relu(bn1(conv1 @ x)); hp = half(h0 + pos)
    tgemm<EPI_BN_RELU><<<gC, blk, TG_SMEM>>>(
        w_conv1, 0, C_, C_, xh, SCN, h0, nullptr, SCN,
        nullptr, bn1_g, bn1_b, bn1_m, bn1_v,
        nullptr, SCN, pos, hp, nullptr, 0, nullptr, nullptr, nullptr, nullptr);

    const float* hbase = h0;
    long hstride = SCN;

    for (int i = 0; i < 4; i++) {
        // [q;val] = [Wqk;Wv] @ hp
        tgemm<EPI_QVAL><<<gQV, blk, TG_SMEM>>>(
            w_qv + (long)i * 81920, 0, 320, C_, hp, SCN, nullptr, val, SCN,
            bv + i * C_, nullptr, nullptr, nullptr, nullptr,
            nullptr, SCN, nullptr, nullptr, nullptr, 0, q, qT, nullptr, nullptr);

        // p~ = fp16(PSCALE * exp(E - groupmax)) + per-group stats
        tgemm<EPI_EXPTILE><<<gE, blk, TG_SMEM>>>(
            qT, SND, N_, D_, q, SDN, nullptr, ath, SNN,
            nullptr, nullptr, nullptr, nullptr, nullptr,
            nullptr, SCN, nullptr, nullptr, nullptr, 0, nullptr, nullptr,
            tstat, nullptr);

        // s[n, t] = exp(tmax - rmax) / rsum
        rowstats_kernel<<<B_ * N_ / 256, blk>>>(tstat, sarr);

        // dh = half(h - (val @ (p~ . s)) / (PSCALE*1e-9 + colsum))
        tgemm<EPI_COLSCALE><<<gC, blk, TG_SMEM>>>(
            val, SCN, C_, N_, ath, SNN, nullptr, dh, SCN,
            nullptr, nullptr, nullptr, nullptr, nullptr,
            hbase, hstride, nullptr, nullptr, nullptr, 0, nullptr, nullptr,
            nullptr, sarr);

        // out[i] = h + relu(bn(Wt @ dh + bt)); hp = half(out[i] + pos) if i<3
        tgemm<EPI_T_UPDATE><<<gC, blk, TG_SMEM>>>(
            w_t + (long)i * C_ * C_, 0, C_, C_, dh, SCN, nullptr, nullptr, 0,
            bt + i * C_, bng + i * C_, bnb + i * C_, bnm + i * C_, bnv + i * C_,
            hbase, hstride, pos, (i < 3) ? hp : nullptr,
            out + (long)i * C_ * N_, SOUT, nullptr, nullptr,
            nullptr, nullptr);

        hbase = out + (long)i * C_ * N_;
        hstride = SOUT;
    }
}

// round 16
// speedup vs baseline: 1.0081x; 1.0081x over previous
#include <cuda_runtime.h>
#include <cuda_fp16.h>
#include <cstdint>

// ---------------------------------------------------------------------------
// PCT position-embedding + 4 offset-attention SA layers. B=8, C=256, D=64,
// N=2048. fp16 mma.sync m16n8k16 (fp32 accum), PSCALE'd softmax probs.
// Softmax-free: energy GEMM emits p~ = PSCALE*exp(e - tilemax) fp16 + tile
// stats; rowstats -> s[n,t]; xr GEMM applies s in fp32 on B fragments
// (s itself can underflow fp16 -- only the product p~*s is fp16-safe).
// Energy A operand loaded straight from q (K-major) via ldmatrix.trans
// (mapping {r0,r2,r1,r3}, validated by round-14/15 identical-output evidence).
// ---------------------------------------------------------------------------

#define B_   8
#define C_   256
#define D_   64
#define N_   2048
#define PSCALE 32768.0f
#define NT_  16                       // N_/128 column tiles

__device__ __half g_pos[B_ * C_ * N_];
__device__ float  g_h0 [B_ * C_ * N_];
__device__ __half g_hp [B_ * C_ * N_];
__device__ __half g_xh [B_ * C_ * N_];
__device__ __half g_q  [B_ * D_ * N_];
__device__ __half g_val[B_ * C_ * N_];
__device__ __half g_dh [B_ * C_ * N_];
__device__ __half g_ath[(long long)B_ * N_ * N_];   // p~ (fp16)
__device__ float2 g_tstat[B_ * NT_ * N_];           // {tilemax, tilesum}
__device__ float  g_s   [B_ * NT_ * N_];            // s[n,t]
__device__ __half g_wh [655360];

__device__ __forceinline__ uint32_t smem_u32(const void* p) {
    return (uint32_t)__cvta_generic_to_shared(p);
}
__device__ __forceinline__ uint32_t h2u(__half2 h) {
    return *reinterpret_cast<uint32_t*>(&h);
}

// ---------------------------------------------------------------------------
// warp-tile compute: 64x32 warp tile, fp16 m16n8k16, fp32 accum.
// SCALE: B fragments scaled by per-k fp32 scales (fp32 mul, round to fp16),
//        column sums of scaled values accumulated into csumF[4].
// ATRANS: A fragments via ldmatrix.trans from a [k][m] tile (stride 136).
// ---------------------------------------------------------------------------
template <bool SCALE, bool ATRANS>
__device__ __forceinline__ void compute_tile(
    const __half* __restrict__ Asb, const __half* __restrict__ Bsb,
    float acc[4][4][4], int lane, int wm0, int wn0,
    const float* __restrict__ sst, float* __restrict__ csumF)
{
    const int tg = lane & 3;
#pragma unroll
    for (int ks = 0; ks < 2; ks++) {
        uint32_t a[4][4];
#pragma unroll
        for (int mt = 0; mt < 4; mt++) {
            if (!ATRANS) {
                const __half* pa = Asb + (wm0 + mt * 16 + (lane & 15)) * 40
                                 + ks * 16 + (lane >> 4) * 8;
                uint32_t ad = smem_u32(pa);
                asm volatile("ldmatrix.sync.aligned.m8n8.x4.shared.b16 {%0,%1,%2,%3}, [%4];"
                    : "=r"(a[mt][0]), "=r"(a[mt][1]), "=r"(a[mt][2]), "=r"(a[mt][3])
                    : "r"(ad));
            } else {
                const __half* pa = Asb
                    + (ks * 16 + (lane & 7) + ((lane >> 3) & 1) * 8) * 136
                    + wm0 + mt * 16 + (lane >> 4) * 8;
                uint32_t ad = smem_u32(pa);
                uint32_t r0, r1, r2, r3;
                asm volatile("ldmatrix.sync.aligned.m8n8.x4.trans.shared.b16 {%0,%1,%2,%3}, [%4];"
                    : "=r"(r0), "=r"(r1), "=r"(r2), "=r"(r3) : "r"(ad));
                a[mt][0] = r0; a[mt][1] = r2; a[mt][2] = r1; a[mt][3] = r3;
            }
        }
        uint32_t b[4][2];
#pragma unroll
        for (int j = 0; j < 2; j++) {
            const __half* pb = Bsb
                + (ks * 16 + (lane & 7) + ((lane >> 3) & 1) * 8) * 136
                + wn0 + j * 16 + (lane >> 4) * 8;
            uint32_t bd = smem_u32(pb);
            uint32_t r0, r1, r2, r3;
            asm volatile("ldmatrix.sync.aligned.m8n8.x4.trans.shared.b16 {%0,%1,%2,%3}, [%4];"
                : "=r"(r0), "=r"(r1), "=r"(r2), "=r"(r3) : "r"(bd));
            b[2 * j][0] = r0; b[2 * j][1] = r1;
            b[2 * j + 1][0] = r2; b[2 * j + 1][1] = r3;
        }
        if (SCALE) {
            // b[nt][0] holds k = ks*16 + 2tg,+1 ; b[nt][1] holds +8,+9
            // fp32 multiply: s may underflow fp16; only p~*s is fp16-safe.
            float2 sA = *reinterpret_cast<const float2*>(&sst[ks * 16 + 2 * tg]);
            float2 sB = *reinterpret_cast<const float2*>(&sst[ks * 16 + 8 + 2 * tg]);
#pragma unroll
            for (int nt = 0; nt < 4; nt++) {
                __half2 h0v = *reinterpret_cast<__half2*>(&b[nt][0]);
                float2 f0 = __half22float2(h0v);
                f0.x *= sA.x; f0.y *= sA.y;
                b[nt][0] = h2u(__floats2half2_rn(f0.x, f0.y));
                __half2 h1v = *reinterpret_cast<__half2*>(&b[nt][1]);
                float2 f1 = __half22float2(h1v);
                f1.x *= sB.x; f1.y *= sB.y;
                b[nt][1] = h2u(__floats2half2_rn(f1.x, f1.y));
                csumF[nt] += (f0.x + f0.y) + (f1.x + f1.y);
            }
        }
#pragma unroll
        for (int mt = 0; mt < 4; mt++)
#pragma unroll
            for (int nt = 0; nt < 4; nt++) {
                asm volatile(
                    "mma.sync.aligned.m16n8k16.row.col.f32.f16.f16.f32 "
                    "{%0,%1,%2,%3}, {%4,%5,%6,%7}, {%8,%9}, {%0,%1,%2,%3};"
                    : "+f"(acc[mt][nt][0]), "+f"(acc[mt][nt][1]),
                      "+f"(acc[mt][nt][2]), "+f"(acc[mt][nt][3])
                    : "r"(a[mt][0]), "r"(a[mt][1]), "r"(a[mt][2]), "r"(a[mt][3]),
                      "r"(b[nt][0]), "r"(b[nt][1]));
            }
    }
}

// ---------------------------------------------------------------------------
// prep kernel: weights + x to fp16, pos (fp16).
// ---------------------------------------------------------------------------
#define SEG_W1   65536L
#define SEG_QV   327680L
#define SEG_WT   262144L
#define SEG_X    ((long)B_ * C_ * N_)
#define PREP_TOT (SEG_W1 + SEG_QV + SEG_WT + SEG_X + SEG_X)

__global__ void prep_kernel(const float* __restrict__ conv1_w,
                            const float* __restrict__ Wqk,
                            const float* __restrict__ Wv,
                            const float* __restrict__ Wt,
                            const float* __restrict__ x,
                            const float* __restrict__ convpos,
                            const float* __restrict__ xyz)
{
    long i = (long)blockIdx.x * 256 + threadIdx.x;
    if (i >= PREP_TOT) return;
    if (i < SEG_W1) {
        g_wh[i] = __float2half_rn(conv1_w[i]);
    } else if (i < SEG_W1 + SEG_QV) {
        long j = i - SEG_W1;
        int layer = (int)(j / 81920);
        long o = j % 81920;
        float v = (o < 16384) ? Wqk[(long)layer * 16384 + o]
                              : Wv[(long)layer * 65536 + (o - 16384)];
        g_wh[i] = __float2half_rn(v);
    } else if (i < SEG_W1 + SEG_QV + SEG_WT) {
        g_wh[i] = __float2half_rn(Wt[i - SEG_W1 - SEG_QV]);
    } else if (i < SEG_W1 + SEG_QV + SEG_WT + SEG_X) {
        long j = i - SEG_W1 - SEG_QV - SEG_WT;
        g_xh[j] = __float2half_rn(x[j]);
    } else {
        long j = i - SEG_W1 - SEG_QV - SEG_WT - SEG_X;
        int n = (int)(j % N_);
        int c = (int)((j / N_) % C_);
        int b = (int)(j / ((long)C_ * N_));
        const float* pp = xyz + ((long)b * N_ + n) * 3;
        g_pos[j] = __float2half_rn(
            convpos[c * 3 + 0] * pp[0] + convpos[c * 3 + 1] * pp[1]
            + convpos[c * 3 + 2] * pp[2]);
    }
}

// ---------------------------------------------------------------------------
// fp16 GEMM, block tile 128x128, 4-stage cp.async ring, 1 barrier/stage.
// ---------------------------------------------------------------------------
enum { EPI_BN_RELU = 0, EPI_QVAL = 1, EPI_EXPTILE = 2, EPI_COLSCALE = 3,
       EPI_T_UPDATE = 4 };

#define TG_STAGES   4
#define TG_AS_STR   (128 * 40)
#define TG_BS_STR   (32 * 136)
#define TG_RING_B   (TG_STAGES * (TG_AS_STR + TG_BS_STR) * 2)
#define TG_CS_B     (TG_RING_B)
#define TG_CSB_B    (TG_CS_B + 16 * 128 * 4)
#define TG_SR_B     (TG_CSB_B + 128 * 4)
#define TG_SMEM     (TG_SR_B + TG_STAGES * 32 * 4)

#define SCN_ ((long)C_ * N_)

template <int EPI>
__global__ void __launch_bounds__(256, 2)
tgemm(const __half* __restrict__ A, long aStride, int M, int K,
      const __half* __restrict__ Bm, long bStride,
      float* __restrict__ Cf, __half* __restrict__ Ch, long cStride,
      const float* __restrict__ bias,
      const float* __restrict__ bng, const float* __restrict__ bnb,
      const float* __restrict__ bnm, const float* __restrict__ bnv,
      const float* __restrict__ hres, long hresStride,
      const __half* __restrict__ posB,
      __half* __restrict__ hpOut,
      float* __restrict__ out2, long out2Stride,
      __half* __restrict__ qB,
      float2* __restrict__ tstatOut, const float* __restrict__ sArr)
{
    constexpr bool ATRANS = (EPI == EPI_EXPTILE);
    constexpr bool SCALE  = (EPI == EPI_COLSCALE);

    extern __shared__ char smd[];
    __half* AsBase = reinterpret_cast<__half*>(smd);
    __half* BsBase = AsBase + TG_STAGES * TG_AS_STR;
    float (*red4)[4] = reinterpret_cast<float(*)[4]>(smd + TG_CS_B);
    float* csb   = reinterpret_cast<float*>(smd + TG_CSB_B);
    float* sring = reinterpret_cast<float*>(smd + TG_SR_B);

    const int bz = blockIdx.z;
    const __half* Ab = A + (long)bz * aStride;
    const __half* Bb = Bm + (long)bz * bStride;
    const float* sBase = SCALE
        ? (sArr + (((long)bz * NT_ + blockIdx.x) << 11)) : nullptr;

    const int m0 = blockIdx.y * 128;
    const int n0 = blockIdx.x * 128;
    const int t  = threadIdx.x;
    const int lane = t & 31;
    const int w    = t >> 5;
    const int g  = lane >> 2, tg = lane & 3;
    const int wm0 = (w >> 2) * 64, wn0 = (w & 3) * 32;

    float acc[4][4][4];
#pragma unroll
    for (int i = 0; i < 4; i++)
#pragma unroll
        for (int j = 0; j < 4; j++)
#pragma unroll
            for (int k = 0; k < 4; k++) acc[i][j][k] = 0.f;

    float csumF[4] = {0.f, 0.f, 0.f, 0.f};

    const int aRow = t >> 2, aCg = (t & 3) * 8;
    const int bRow = t >> 4, bCg = (t & 15) * 8;
    const int nStages = K >> 5;

    // prologue
#pragma unroll
    for (int s = 0; s < TG_STAGES - 1; s++) {
        if (s < nStages) {
            const int k0 = s * 32;
            __half* As = AsBase + s * TG_AS_STR;
            __half* Bs = BsBase + s * TG_BS_STR;
            if (!ATRANS) {
#pragma unroll
                for (int h = 0; h < 2; h++) {
                    int row = aRow + h * 64;
                    if (m0 + row < M) {
                        uint32_t dst = smem_u32(As + row * 40 + aCg);
                        const __half* src = Ab + (long)(m0 + row) * K + k0 + aCg;
                        asm volatile("cp.async.cg.shared.global [%0], [%1], 16;" :: "r"(dst), "l"(src));
                    }
                }
            } else {
#pragma unroll
                for (int h = 0; h < 2; h++) {
                    int row = bRow + h * 16;
                    uint32_t dst = smem_u32(As + row * 136 + bCg);
                    const __half* src = Ab + (long)(k0 + row) * N_ + m0 + bCg;
                    asm volatile("cp.async.cg.shared.global [%0], [%1], 16;" :: "r"(dst), "l"(src));
                }
            }
#pragma unroll
            for (int h = 0; h < 2; h++) {
                int row = bRow + h * 16;
                uint32_t dst = smem_u32(Bs + row * 136 + bCg);
                const __half* src = Bb + (long)(k0 + row) * N_ + n0 + bCg;
                asm volatile("cp.async.cg.shared.global [%0], [%1], 16;" :: "r"(dst), "l"(src));
            }
            if (SCALE && t < 8) {
                uint32_t dst = smem_u32(sring + s * 32 + t * 4);
                const float* src = sBase + k0 + t * 4;
                asm volatile("cp.async.cg.shared.global [%0], [%1], 16;" :: "r"(dst), "l"(src));
            }
        }
        asm volatile("cp.async.commit_group;");
    }

    for (int s = 0; s < nStages; s++) {
        const int buf = s & (TG_STAGES - 1);
        asm volatile("cp.async.wait_group %0;" :: "n"(TG_STAGES - 2));
        __syncthreads();

        const int sn = s + TG_STAGES - 1;
        if (sn < nStages) {
            const int k0 = sn * 32, nb = sn & (TG_STAGES - 1);
            __half* As = AsBase + nb * TG_AS_STR;
            __half* Bs = BsBase + nb * TG_BS_STR;
            if (!ATRANS) {
#pragma unroll
                for (int h = 0; h < 2; h++) {
                    int row = aRow + h * 64;
                    if (m0 + row < M) {
                        uint32_t dst = smem_u32(As + row * 40 + aCg);
                        const __half* src = Ab + (long)(m0 + row) * K + k0 + aCg;
                        asm volatile("cp.async.cg.shared.global [%0], [%1], 16;" :: "r"(dst), "l"(src));
                    }
                }
            } else {
#pragma unroll
                for (int h = 0; h < 2; h++) {
                    int row = bRow + h * 16;
                    uint32_t dst = smem_u32(As + row * 136 + bCg);
                    const __half* src = Ab + (long)(k0 + row) * N_ + m0 + bCg;
                    asm volatile("cp.async.cg.shared.global [%0], [%1], 16;" :: "r"(dst), "l"(src));
                }
            }
#pragma unroll
            for (int h = 0; h < 2; h++) {
                int row = bRow + h * 16;
                uint32_t dst = smem_u32(Bs + row * 136 + bCg);
                const __half* src = Bb + (long)(k0 + row) * N_ + n0 + bCg;
                asm volatile("cp.async.cg.shared.global [%0], [%1], 16;" :: "r"(dst), "l"(src));
            }
            if (SCALE && t < 8) {
                uint32_t dst = smem_u32(sring + nb * 32 + t * 4);
                const float* src = sBase + k0 + t * 4;
                asm volatile("cp.async.cg.shared.global [%0], [%1], 16;" :: "r"(dst), "l"(src));
            }
        }
        asm volatile("cp.async.commit_group;");

        const __half* AsC = AsBase + buf * TG_AS_STR;
        const __half* BsC = BsBase + buf * TG_BS_STR;
        compute_tile<SCALE, ATRANS>(AsC, BsC, acc, lane, wm0, wn0,
                                    sring + buf * 32, csumF);
    }

    const long cOff = (long)bz * cStride;

    // ------- EXPTILE epilogue -------
    if (EPI == EPI_EXPTILE) {
        __syncthreads();
        float tmaxv[4][2];
#pragma unroll
        for (int mt = 0; mt < 4; mt++)
#pragma unroll
            for (int hf = 0; hf < 2; hf++) {
                float mval = -3.4e38f;
#pragma unroll
                for (int nt = 0; nt < 4; nt++) {
                    mval = fmaxf(mval, acc[mt][nt][hf * 2 + 0]);
                    mval = fmaxf(mval, acc[mt][nt][hf * 2 + 1]);
                }
                mval = fmaxf(mval, __shfl_xor_sync(0xffffffffu, mval, 1));
                mval = fmaxf(mval, __shfl_xor_sync(0xffffffffu, mval, 2));
                tmaxv[mt][hf] = mval;
            }
        if (tg == 0) {
#pragma unroll
            for (int mt = 0; mt < 4; mt++)
#pragma unroll
                for (int hf = 0; hf < 2; hf++)
                    red4[wm0 + mt * 16 + g + hf * 8][w & 3] = tmaxv[mt][hf];
        }
        __syncthreads();
#pragma unroll
        for (int mt = 0; mt < 4; mt++)
#pragma unroll
            for (int hf = 0; hf < 2; hf++) {
                const float* rr = red4[wm0 + mt * 16 + g + hf * 8];
                tmaxv[mt][hf] = fmaxf(fmaxf(rr[0], rr[1]), fmaxf(rr[2], rr[3]));
            }
        __syncthreads();
        float psum[4][2];
#pragma unroll
        for (int mt = 0; mt < 4; mt++)
#pragma unroll
            for (int hf = 0; hf < 2; hf++) {
                float s2 = 0.f;
#pragma unroll
                for (int nt = 0; nt < 4; nt++) {
                    float e0 = __expf(acc[mt][nt][hf * 2 + 0] - tmaxv[mt][hf]);
                    float e1 = __expf(acc[mt][nt][hf * 2 + 1] - tmaxv[mt][hf]);
                    acc[mt][nt][hf * 2 + 0] = e0;
                    acc[mt][nt][hf * 2 + 1] = e1;
                    s2 += e0 + e1;
                }
                s2 += __shfl_xor_sync(0xffffffffu, s2, 1);
                s2 += __shfl_xor_sync(0xffffffffu, s2, 2);
                psum[mt][hf] = s2;
            }
        if (tg == 0) {
#pragma unroll
            for (int mt = 0; mt < 4; mt++)
#pragma unroll
                for (int hf = 0; hf < 2; hf++)
                    red4[wm0 + mt * 16 + g + hf * 8][w & 3] = psum[mt][hf];
        }
        __syncthreads();
#pragma unroll
        for (int mt = 0; mt < 4; mt++)
#pragma unroll
            for (int hf = 0; hf < 2; hf++) {
                const int rl = wm0 + mt * 16 + g + hf * 8;
                const int r = m0 + rl;
#pragma unroll
                for (int nt = 0; nt < 4; nt++) {
                    const int cb = n0 + wn0 + nt * 8 + 2 * tg;
                    *reinterpret_cast<__half2*>(Ch + cOff + (long)r * N_ + cb) =
                        __floats2half2_rn(PSCALE * acc[mt][nt][hf * 2 + 0],
                                          PSCALE * acc[mt][nt][hf * 2 + 1]);
                }
                if ((w & 3) == 0 && tg == 0) {
                    const float* rr = red4[rl];
                    tstatOut[(((long)bz * NT_ + blockIdx.x) << 11) + r] =
                        make_float2(tmaxv[mt][hf], rr[0] + rr[1] + rr[2] + rr[3]);
                }
            }
        return;
    }

    if (EPI == EPI_COLSCALE) {
        __syncthreads();
#pragma unroll
        for (int nt = 0; nt < 4; nt++) {
            csumF[nt] += __shfl_xor_sync(0xffffffffu, csumF[nt], 1);
            csumF[nt] += __shfl_xor_sync(0xffffffffu, csumF[nt], 2);
        }
        if (w < 4 && tg == 0) {
#pragma unroll
            for (int nt = 0; nt < 4; nt++)
                csb[wn0 + nt * 8 + g] = 1.f / (PSCALE * 1e-9f + csumF[nt]);
        }
        __syncthreads();
    }

#pragma unroll
    for (int mt = 0; mt < 4; mt++) {
#pragma unroll
        for (int half_ = 0; half_ < 2; half_++) {
            const int r = m0 + wm0 + mt * 16 + g + half_ * 8;
            if (r >= M) continue;

            float sc = 1.f, sh = 0.f, bsv = 0.f;
            if (EPI == EPI_BN_RELU || EPI == EPI_T_UPDATE) {
                float inv = rsqrtf(bnv[r] + 1e-5f);
                sc = bng[r] * inv; sh = bnb[r] - bnm[r] * sc;
            }
            if (EPI == EPI_T_UPDATE) bsv = bias[r];

#pragma unroll
            for (int nt = 0; nt < 4; nt++) {
                const int cb = n0 + wn0 + nt * 8 + 2 * tg;
                float v0 = acc[mt][nt][half_ * 2 + 0];
                float v1 = acc[mt][nt][half_ * 2 + 1];
                long rowoff = (long)r * N_ + cb;

                if (EPI == EPI_BN_RELU) {
                    v0 = fmaxf(fmaf(v0, sc, sh), 0.f);
                    v1 = fmaxf(fmaf(v1, sc, sh), 0.f);
                    *reinterpret_cast<float2*>(Cf + cOff + rowoff) = make_float2(v0, v1);
                    const __half* pb = posB + (long)bz * SCN_;
                    float2 p2 = __half22float2(
                        *reinterpret_cast<const __half2*>(pb + rowoff));
                    __half2* hbp = reinterpret_cast<__half2*>(
                        hpOut + (long)bz * SCN_ + rowoff);
                    *hbp = __floats2half2_rn(v0 + p2.x, v1 + p2.y);
                } else if (EPI == EPI_QVAL) {
                    if (r < 64) {
                        __half* qb = qB + (long)bz * ((long)D_ * N_);
                        *reinterpret_cast<__half2*>(qb + (long)r * N_ + cb) =
                            __floats2half2_rn(v0, v1);
                    } else {
                        float bv2 = bias[r - 64];
                        long vo = (long)(r - 64) * N_ + cb;
                        *reinterpret_cast<__half2*>(Ch + cOff + vo) =
                            __floats2half2_rn(v0 + bv2, v1 + bv2);
                    }
                } else if (EPI == EPI_COLSCALE) {
                    float i0 = csb[cb - n0], i1 = csb[cb - n0 + 1];
                    const float* hb = hres + (long)bz * hresStride;
                    float2 h2 = *reinterpret_cast<const float2*>(hb + rowoff);
                    *reinterpret_cast<__half2*>(Ch + cOff + rowoff) =
                        __floats2half2_rn(h2.x - v0 * i0, h2.y - v1 * i1);
                } else { // EPI_T_UPDATE
                    v0 = fmaxf(fmaf(v0 + bsv, sc, sh), 0.f);
                    v1 = fmaxf(fmaf(v1 + bsv, sc, sh), 0.f);
                    const float* hb = hres + (long)bz * hresStride;
                    float2 h2 = *reinterpret_cast<const float2*>(hb + rowoff);
                    float o0 = v0 + h2.x, o1 = v1 + h2.y;
                    float* ob = out2 + (long)bz * out2Stride;
                    *reinterpret_cast<float2*>(ob + rowoff) = make_float2(o0, o1);
                    if (hpOut) {
                        const __half* pb = posB + (long)bz * SCN_;
                        float2 p2 = __half22float2(
                            *reinterpret_cast<const __half2*>(pb + rowoff));
                        __half2* hb2 = reinterpret_cast<__half2*>(
                            hpOut + (long)bz * SCN_ + rowoff);
                        *hb2 = __floats2half2_rn(o0 + p2.x, o1 + p2.y);
                    }
                }
            }
        }
    }
}

// ---------------------------------------------------------------------------
// rowstats: per (b, n) row, combine 16 tile stats -> s[n, t].
// ---------------------------------------------------------------------------
__global__ void __launch_bounds__(256)
rowstats_kernel(const float2* __restrict__ tstat, float* __restrict__ sarr)
{
    int idx = blockIdx.x * 256 + threadIdx.x;
    int b = idx >> 11, n = idx & 2047;
    float tm[NT_], ts[NT_];
    float rmax = -3.4e38f;
#pragma unroll
    for (int t = 0; t < NT_; t++) {
        float2 v = tstat[(((long)b * NT_ + t) << 11) + n];
        tm[t] = v.x; ts[t] = v.y;
        rmax = fmaxf(rmax, v.x);
    }
    float rsum = 0.f;
#pragma unroll
    for (int t = 0; t < NT_; t++) {
        tm[t] = __expf(tm[t] - rmax);
        rsum += ts[t] * tm[t];
    }
    float rinv = 1.f / rsum;
#pragma unroll
    for (int t = 0; t < NT_; t++)
        sarr[(((long)b * NT_ + t) << 11) + n] = tm[t] * rinv;
}

// ---------------------------------------------------------------------------
extern "C" void kernel_launch(void* const* d_in, const int* in_sizes, int n_in,
                              void* d_out, int out_size)
{
    (void)in_sizes; (void)n_in; (void)out_size;

    const float* x       = (const float*)d_in[0];
    const float* xyz     = (const float*)d_in[1];
    const float* conv1_w = (const float*)d_in[2];
    const float* convpos = (const float*)d_in[3];
    const float* bn1_g   = (const float*)d_in[4];
    const float* bn1_b   = (const float*)d_in[5];
    const float* bn1_m   = (const float*)d_in[6];
    const float* bn1_v   = (const float*)d_in[7];
    const float* Wqk     = (const float*)d_in[8];
    const float* Wv      = (const float*)d_in[9];
    const float* bv      = (const float*)d_in[10];
    const float* Wt      = (const float*)d_in[11];
    const float* bt      = (const float*)d_in[12];
    const float* bng     = (const float*)d_in[13];
    const float* bnb     = (const float*)d_in[14];
    const float* bnm     = (const float*)d_in[15];
    const float* bnv     = (const float*)d_in[16];
    float* out = (float*)d_out;

    float  *h0, *sarr;
    float2 *tstat;
    __half *pos, *hp, *xh, *q, *val, *dh, *ath, *wh;
    cudaGetSymbolAddress((void**)&pos,   g_pos);
    cudaGetSymbolAddress((void**)&h0,    g_h0);
    cudaGetSymbolAddress((void**)&hp,    g_hp);
    cudaGetSymbolAddress((void**)&xh,    g_xh);
    cudaGetSymbolAddress((void**)&q,     g_q);
    cudaGetSymbolAddress((void**)&val,   g_val);
    cudaGetSymbolAddress((void**)&dh,    g_dh);
    cudaGetSymbolAddress((void**)&ath,   g_ath);
    cudaGetSymbolAddress((void**)&wh,    g_wh);
    cudaGetSymbolAddress((void**)&tstat, g_tstat);
    cudaGetSymbolAddress((void**)&sarr,  g_s);

    cudaFuncSetAttribute(tgemm<EPI_BN_RELU>,  cudaFuncAttributeMaxDynamicSharedMemorySize, TG_SMEM);
    cudaFuncSetAttribute(tgemm<EPI_QVAL>,     cudaFuncAttributeMaxDynamicSharedMemorySize, TG_SMEM);
    cudaFuncSetAttribute(tgemm<EPI_EXPTILE>,  cudaFuncAttributeMaxDynamicSharedMemorySize, TG_SMEM);
    cudaFuncSetAttribute(tgemm<EPI_COLSCALE>, cudaFuncAttributeMaxDynamicSharedMemorySize, TG_SMEM);
    cudaFuncSetAttribute(tgemm<EPI_T_UPDATE>, cudaFuncAttributeMaxDynamicSharedMemorySize, TG_SMEM);

    const long SCN = (long)C_ * N_;
    const long SDN = (long)D_ * N_;
    const long SNN = (long)N_ * N_;
    const long SOUT = (long)4 * C_ * N_;

    __half* w_conv1 = wh;
    __half* w_qv    = wh + SEG_W1;
    __half* w_t     = wh + SEG_W1 + SEG_QV;

    dim3 blk(256);
    dim3 gC (N_ / 128, 2, B_);
    dim3 gQV(N_ / 128, 3, B_);
    dim3 gE (N_ / 128, N_ / 128, B_);

    prep_kernel<<<(int)((PREP_TOT + 255) / 256), blk>>>(conv1_w, Wqk, Wv, Wt, x,
                                                        convpos, xyz);

    // h0 = relu(bn1(conv1 @ x)); hp = half(h0 + pos)
    tgemm<EPI_BN_RELU><<<gC, blk, TG_SMEM>>>(
        w_conv1, 0, C_, C_, xh, SCN, h0, nullptr, SCN,
        nullptr, bn1_g, bn1_b, bn1_m, bn1_v,
        nullptr, SCN, pos, hp, nullptr, 0, nullptr, nullptr, nullptr);

    const float* hbase = h0;
    long hstride = SCN;

    for (int i = 0; i < 4; i++) {
        // [q;val] = [Wqk;Wv] @ hp   (q written K-major only; no qT)
        tgemm<EPI_QVAL><<<gQV, blk, TG_SMEM>>>(
            w_qv + (long)i * 81920, 0, 320, C_, hp, SCN, nullptr, val, SCN,
            bv + i * C_, nullptr, nullptr, nullptr, nullptr,
            nullptr, SCN, nullptr, nullptr, nullptr, 0, q, nullptr, nullptr);

        // p~ = fp16(PSCALE * exp(E - tilemax)) + per-tile stats
        // A = q via ldmatrix.trans (K-major), B = q
        tgemm<EPI_EXPTILE><<<gE, blk, TG_SMEM>>>(
            q, SDN, N_, D_, q, SDN, nullptr, ath, SNN,
            nullptr, nullptr, nullptr, nullptr, nullptr,
            nullptr, SCN, nullptr, nullptr, nullptr, 0, nullptr,
            tstat, nullptr);

        // s[n, t] = exp(tmax - rmax) / rsum
        rowstats_kernel<<<B_ * N_ / 256, blk>>>(tstat, sarr);

        // dh = half(h - (val @ (p~ . s)) / (PSCALE*1e-9 + colsum))
        tgemm<EPI_COLSCALE><<<gC, blk, TG_SMEM>>>(
            val, SCN, C_, N_, ath, SNN, nullptr, dh, SCN,
            nullptr, nullptr, nullptr, nullptr, nullptr,
            hbase, hstride, nullptr, nullptr, nullptr, 0, nullptr,
            nullptr, sarr);

        // out[i] = h + relu(bn(Wt @ dh + bt)); hp = half(out[i] + pos) if i<3
        tgemm<EPI_T_UPDATE><<<gC, blk, TG_SMEM>>>(
            w_t + (long)i * C_ * C_, 0, C_, C_, dh, SCN, nullptr, nullptr, 0,
            bt + i * C_, bng + i * C_, bnb + i * C_, bnm + i * C_, bnv + i * C_,
            hbase, hstride, pos, (i < 3) ? hp : nullptr,
            out + (long)i * C_ * N_, SOUT, nullptr,
            nullptr, nullptr);

        hbase = out + (long)i * C_ * N_;
        hstride = SOUT;
    }
}